// round 11
// baseline (speedup 1.0000x reference)
#include <cuda_runtime.h>
#include <cuda_bf16.h>
#include <math.h>
#include <cstdint>

// Problem dims (fixed by the dataset)
#define BB 64
#define SS 1024
#define HH 512
#define AA 128
#define DD 256
#define H3 1536   // 3*HH

// ---------------- scratch (no allocations allowed -> device globals) ----------
__device__ float g_dec[BB * AA];
__device__ float g_scores[BB * SS];
__device__ float g_probs[BB * SS];
__device__ float g_att[BB * HH];
__device__ float g_p0[BB * H3];   // gi partial (K-half 0)
__device__ float g_p1[BB * H3];   // gi partial (K-half 1)
__device__ float g_q0[BB * H3];   // gh partial (K-half 0)
__device__ float g_q1[BB * H3];   // gh partial (K-half 1)
__device__ __align__(32) uint32_t g_We_bf[AA * HH / 2];   // We bf16 [a][k]

__device__ __forceinline__ float fast_tanh(float x) {
    float r;
    asm("tanh.approx.f32 %0, %1;" : "=f"(r) : "f"(x));
    return r;
}
__device__ __forceinline__ uint32_t smem_u32(const void* p) {
    uint32_t a;
    asm("{ .reg .u64 t; cvta.to.shared.u64 t, %1; cvt.u32.u64 %0, t; }"
        : "=r"(a) : "l"(p));
    return a;
}
__device__ __forceinline__ uint32_t pack_bf(float x, float y) {
    uint32_t r;
    asm("cvt.rn.bf16x2.f32 %0, %1, %2;" : "=r"(r) : "f"(y), "f"(x));
    return r;
}

// ---------------- K0a: convert We to bf16 once --------------------------------
__global__ void k0_convW(const float* __restrict__ We) {
    const int base = (blockIdx.x * 256 + threadIdx.x) * 4;
    const float2* W2 = (const float2*)We;
    #pragma unroll
    for (int i = 0; i < 4; i++) {
        float2 v = W2[base + i];
        g_We_bf[base + i] = pack_bf(v.x, v.y);
    }
}

// ---------------- K1: dec_proj[b,a] = states[b]·Wd[a] + bd[a] + be[a] ---------
// grid (BB, 8), 128 threads: warp w handles a = by*16 + w*4 + i, float4 loads.
__global__ __launch_bounds__(128) void k1_decproj(const float* __restrict__ states,
                                                  const float* __restrict__ Wd,
                                                  const float* __restrict__ bd,
                                                  const float* __restrict__ be) {
    const int b = blockIdx.x;
    const int a0 = blockIdx.y * 16 + (threadIdx.x >> 5) * 4;
    const int lane = threadIdx.x & 31;

    const float4* st4 = (const float4*)(states + b * HH);
    float4 st[4];
    #pragma unroll
    for (int j = 0; j < 4; j++) st[j] = st4[lane + 32 * j];

    #pragma unroll
    for (int i = 0; i < 4; i++) {
        const int a = a0 + i;
        const float4* w4 = (const float4*)(Wd + (size_t)a * HH);
        float s = 0.f;
        #pragma unroll
        for (int j = 0; j < 4; j++) {
            const float4 w = w4[lane + 32 * j];
            s += st[j].x * w.x + st[j].y * w.y + st[j].z * w.z + st[j].w * w.w;
        }
        #pragma unroll
        for (int o = 16; o; o >>= 1) s += __shfl_xor_sync(0xffffffffu, s, o);
        if (lane == 0) g_dec[b * AA + a] = s + bd[a] + be[a];
    }
}

// ======= K2b: fused fp32->bf16 mma.sync GEMM (conversion in-kernel) ===========
// Block: 128 s x 128 a, K=512 in 8 chunks of 64 (bf16 tiles 128 B/row, SW128).
// Per chunk: cp.async fp32 E (padded 272B rows, conflict-free) -> convert to
// bf16 smem between syncs (transient regs only) -> identical MMA mapping.
// Loads for chunk c+1 overlap MMA on chunk c. W arrives bf16 via cp.async.
#define K2_FPAD   272                    // fp32 staging row stride (bytes)
#define K2_EOFF   34816                  // 128*272 fp32 staging
#define K2_WOFF   (K2_EOFF + 2 * 16384)  // 67584
#define K2_SXTRA  (K2_WOFF + 2 * 16384)  // 100352: sdec/swv/sp
#define K2_SMEMB  (K2_SXTRA + 2048)      // 102400 bytes -> 2 CTAs/SM

__device__ __forceinline__ void cp16(uint32_t daddr, const void* src) {
    asm volatile("cp.async.cg.shared.global [%0], [%1], 16;" :: "r"(daddr), "l"(src));
}
__device__ __forceinline__ void cp_commit() {
    asm volatile("cp.async.commit_group;" ::: "memory");
}
__device__ __forceinline__ void ldsm4(uint32_t* r, uint32_t addr) {
    asm volatile("ldmatrix.sync.aligned.m8n8.x4.shared.b16 {%0,%1,%2,%3}, [%4];"
                 : "=r"(r[0]), "=r"(r[1]), "=r"(r[2]), "=r"(r[3]) : "r"(addr));
}
__device__ __forceinline__ void sts128(uint32_t addr, uint32_t a, uint32_t b,
                                       uint32_t c, uint32_t d) {
    asm volatile("st.shared.v4.b32 [%0], {%1,%2,%3,%4};"
                 :: "r"(addr), "r"(a), "r"(b), "r"(c), "r"(d));
}
__device__ __forceinline__ void lds128(float4& v, uint32_t addr) {
    asm volatile("ld.shared.v4.f32 {%0,%1,%2,%3}, [%4];"
                 : "=f"(v.x), "=f"(v.y), "=f"(v.z), "=f"(v.w) : "r"(addr));
}
__device__ __forceinline__ void mma_bf16(float* d, const uint32_t* a,
                                         uint32_t b0, uint32_t b1) {
    asm volatile(
        "mma.sync.aligned.m16n8k16.row.col.f32.bf16.bf16.f32 "
        "{%0,%1,%2,%3}, {%4,%5,%6,%7}, {%8,%9}, {%0,%1,%2,%3};"
        : "+f"(d[0]), "+f"(d[1]), "+f"(d[2]), "+f"(d[3])
        : "r"(a[0]), "r"(a[1]), "r"(a[2]), "r"(a[3]), "r"(b0), "r"(b1));
}

__global__ __launch_bounds__(256, 2) void k2b_scores(const float* __restrict__ enc,
                                                     const float* __restrict__ Wv,
                                                     const float* __restrict__ bv) {
    extern __shared__ float sm[];
    const uint32_t smem_base = smem_u32(sm);
    float* sdec = sm + K2_SXTRA / 4;
    float* swv  = sdec + 128;
    float* sp   = swv + 128;   // 2*128 floats

    const int b  = blockIdx.y;
    const int s0 = blockIdx.x * 128;
    const int tid = threadIdx.x;
    const int lane = tid & 31;
    const int wid = tid >> 5;
    const int warp_s = wid & 3;
    const int warp_a = wid >> 2;
    const int ms = warp_s * 32;
    const int na = warp_a * 64;

    if (tid < 128) {
        sdec[tid] = g_dec[b * AA + tid];
        swv[tid]  = Wv[tid];
    }

    const char* encb = (const char*)(enc + ((size_t)b * SS + s0) * HH);
    const char* web  = (const char*)g_We_bf;
    const int r_st  = tid >> 3;   // 0..31 (+32i)
    const int sg_st = tid & 7;    // 16B segment 0..7

    float acc[2][8][4];
    #pragma unroll
    for (int f = 0; f < 2; f++)
        #pragma unroll
        for (int g = 0; g < 8; g++)
            #pragma unroll
            for (int q = 0; q < 4; q++) acc[f][g][q] = 0.f;

    // fp32 E chunk load: 128 rows x 256B (16 segs of 16B), padded rows (272B)
    auto issueE = [&](int c) {
        #pragma unroll
        for (int i = 0; i < 8; i++) {
            const int g2 = i * 256 + tid;
            const int r = g2 >> 4;
            const int s = g2 & 15;
            cp16(smem_base + r * K2_FPAD + s * 16,
                 encb + (size_t)r * 2048 + c * 256 + s * 16);
        }
    };
    // W bf16 chunk load (swizzled, as before)
    auto issueW = [&](int c) {
        const int buf = c & 1;
        #pragma unroll
        for (int i = 0; i < 4; i++) {
            const int r = r_st + i * 32;
            const uint32_t sw = (uint32_t)(r * 128 + ((sg_st ^ (r & 7)) << 4));
            cp16(smem_base + K2_WOFF + buf * 16384 + sw,
                 web + (size_t)r * 1024 + c * 128 + sg_st * 16);
        }
    };

    // convert indices: thread -> (row rr, half) of the fp32 chunk
    const int rr   = tid & 127;
    const int half = tid >> 7;
    const uint32_t fsrc = smem_base + rr * K2_FPAD + half * 128;

    issueW(0);
    issueE(0);
    cp_commit();

    #pragma unroll
    for (int c = 0; c < 8; c++) {
        asm volatile("cp.async.wait_group 0;" ::: "memory");
        __syncthreads();

        // convert fbuf (fp32) -> ebuf[c&1] (bf16, SW128): transient regs only
        {
            float4 f[8];
            #pragma unroll
            for (int i = 0; i < 8; i++) lds128(f[i], fsrc + i * 16);
            uint32_t u[16];
            #pragma unroll
            for (int i = 0; i < 8; i++) {
                u[2 * i]     = pack_bf(f[i].x, f[i].y);
                u[2 * i + 1] = pack_bf(f[i].z, f[i].w);
            }
            const uint32_t ebase = smem_base + K2_EOFF + (c & 1) * 16384 + rr * 128;
            #pragma unroll
            for (int j2 = 0; j2 < 4; j2++) {
                const int seg = half * 4 + j2;
                sts128(ebase + ((seg ^ (rr & 7)) << 4),
                       u[4 * j2], u[4 * j2 + 1], u[4 * j2 + 2], u[4 * j2 + 3]);
            }
        }
        __syncthreads();

        if (c < 7) { issueE(c + 1); issueW(c + 1); cp_commit(); }

        const uint32_t Eb = smem_base + K2_EOFF + (c & 1) * 16384;
        const uint32_t Wb = smem_base + K2_WOFF + (c & 1) * 16384;
        #pragma unroll
        for (int ks = 0; ks < 4; ks++) {
            uint32_t afr[2][4];
            #pragma unroll
            for (int f = 0; f < 2; f++) {
                const int row = ms + f * 16 + (lane & 15);
                const int seg = ks * 2 + (lane >> 4);
                ldsm4(afr[f], Eb + row * 128 + ((seg ^ (row & 7)) << 4));
            }
            #pragma unroll
            for (int g2 = 0; g2 < 4; g2++) {
                const int row = na + g2 * 16 + ((lane >> 4) << 3) + (lane & 7);
                const int seg = ks * 2 + ((lane >> 3) & 1);
                uint32_t bfr[4];
                ldsm4(bfr, Wb + row * 128 + ((seg ^ (row & 7)) << 4));
                mma_bf16(acc[0][2 * g2],     afr[0], bfr[0], bfr[1]);
                mma_bf16(acc[0][2 * g2 + 1], afr[0], bfr[2], bfr[3]);
                mma_bf16(acc[1][2 * g2],     afr[1], bfr[0], bfr[1]);
                mma_bf16(acc[1][2 * g2 + 1], afr[1], bfr[2], bfr[3]);
            }
        }
    }

    // epilogue: tanh(acc + dec) * wv, reduce over a
    #pragma unroll
    for (int f = 0; f < 2; f++) {
        float pl = 0.f, ph = 0.f;
        #pragma unroll
        for (int g = 0; g < 8; g++) {
            const int a0 = warp_a * 64 + g * 8 + (lane & 3) * 2;
            const float d0 = sdec[a0], d1 = sdec[a0 + 1];
            const float w0 = swv[a0],  w1 = swv[a0 + 1];
            pl += fast_tanh(acc[f][g][0] + d0) * w0 + fast_tanh(acc[f][g][1] + d1) * w1;
            ph += fast_tanh(acc[f][g][2] + d0) * w0 + fast_tanh(acc[f][g][3] + d1) * w1;
        }
        pl += __shfl_xor_sync(0xffffffffu, pl, 1);
        pl += __shfl_xor_sync(0xffffffffu, pl, 2);
        ph += __shfl_xor_sync(0xffffffffu, ph, 1);
        ph += __shfl_xor_sync(0xffffffffu, ph, 2);
        if ((lane & 3) == 0) {
            const int sl = ms + f * 16 + (lane >> 2);
            sp[warp_a * 128 + sl]     = pl;
            sp[warp_a * 128 + sl + 8] = ph;
        }
    }
    __syncthreads();
    if (tid < 128)
        g_scores[b * SS + s0 + tid] = sp[tid] + sp[128 + tid] + bv[0];
}

// ---------------- K3a: softmax over seq per batch (+ zero g_att) --------------
// grid BB, block 1024: one element per thread, shuffle reductions.
__global__ __launch_bounds__(1024) void k3a_softmax() {
    const int b = blockIdx.x, tid = threadIdx.x;
    const int lane = tid & 31, warp = tid >> 5;
    __shared__ float red[32];
    __shared__ float bcast;

    if (tid < HH) g_att[b * HH + tid] = 0.f;

    float v = g_scores[b * SS + tid];

    // --- max ---
    float m = v;
    #pragma unroll
    for (int o = 16; o; o >>= 1) m = fmaxf(m, __shfl_xor_sync(0xffffffffu, m, o));
    if (lane == 0) red[warp] = m;
    __syncthreads();
    if (warp == 0) {
        float t = red[lane];
        #pragma unroll
        for (int o = 16; o; o >>= 1) t = fmaxf(t, __shfl_xor_sync(0xffffffffu, t, o));
        if (lane == 0) bcast = t;
    }
    __syncthreads();
    const float mx = bcast;

    // --- sum ---
    const float e = expf(v - mx);
    float s = e;
    #pragma unroll
    for (int o = 16; o; o >>= 1) s += __shfl_xor_sync(0xffffffffu, s, o);
    __syncthreads();
    if (lane == 0) red[warp] = s;
    __syncthreads();
    if (warp == 0) {
        float t = red[lane];
        #pragma unroll
        for (int o = 16; o; o >>= 1) t += __shfl_xor_sync(0xffffffffu, t, o);
        if (lane == 0) bcast = 1.f / t;
    }
    __syncthreads();
    g_probs[b * SS + tid] = e * bcast;
}

// ---------------- K3b: attention from fp32 enc (proven round-2 version) -------
// grid (HH/128=4, SS/256=4, BB), 256 threads, float4 loads.
__global__ __launch_bounds__(256) void k3b_att(const float* __restrict__ enc) {
    const int b  = blockIdx.z;
    const int sb = blockIdx.y;
    const int hb = blockIdx.x;
    const int lane = threadIdx.x & 31;
    const int srow = threadIdx.x >> 5;
    const float* e = enc + ((size_t)b * SS + sb * 256 + srow) * HH + hb * 128 + lane * 4;
    const float* pr = g_probs + b * SS + sb * 256 + srow;

    float4 a0 = {0.f, 0.f, 0.f, 0.f}, a1 = {0.f, 0.f, 0.f, 0.f};
    #pragma unroll 4
    for (int i = 0; i < 32; i += 2) {
        const float p0 = pr[i * 8];
        const float p1 = pr[(i + 1) * 8];
        const float4 v0 = *(const float4*)(e + (size_t)i * 8 * HH);
        const float4 v1 = *(const float4*)(e + (size_t)(i + 1) * 8 * HH);
        a0.x = fmaf(p0, v0.x, a0.x); a0.y = fmaf(p0, v0.y, a0.y);
        a0.z = fmaf(p0, v0.z, a0.z); a0.w = fmaf(p0, v0.w, a0.w);
        a1.x = fmaf(p1, v1.x, a1.x); a1.y = fmaf(p1, v1.y, a1.y);
        a1.z = fmaf(p1, v1.z, a1.z); a1.w = fmaf(p1, v1.w, a1.w);
    }
    a0.x += a1.x; a0.y += a1.y; a0.z += a1.z; a0.w += a1.w;

    __shared__ float red[8][32][4];
    red[srow][lane][0] = a0.x;
    red[srow][lane][1] = a0.y;
    red[srow][lane][2] = a0.z;
    red[srow][lane][3] = a0.w;
    __syncthreads();
    if (threadIdx.x < 128) {
        const int l = threadIdx.x & 31;
        const int comp = threadIdx.x >> 5;
        float s = 0.f;
        #pragma unroll
        for (int r = 0; r < 8; r++) s += red[r][l][comp];
        atomicAdd(&g_att[b * HH + hb * 128 + l * 4 + comp], s);
    }
}

// ---------------- K4: gate GEMMs, phase x K-half split, partial buffers -------
// grid (96, 4): y>>1 = phase (0: gi, 1: gh), y&1 = K-half. No atomics:
// each (phase, half) writes its own partial buffer; k5 sums them + biases.
__global__ __launch_bounds__(256) void k4_gemm(const float* __restrict__ inputs,
                                               const float* __restrict__ states,
                                               const float* __restrict__ W_ih,
                                               const float* __restrict__ W_hh) {
    const int j0 = blockIdx.x * 16;
    const int phase = blockIdx.y >> 1;
    const int half  = blockIdx.y & 1;
    const int tid = threadIdx.x;
    const int tx = tid & 15;
    const int tb = tid >> 4;
    const int j = j0 + tx;
    __shared__ float Xs[64][65];
    __shared__ float Wsm[64][17];

    float acc[4] = {0.f, 0.f, 0.f, 0.f};
    if (phase == 0) {
        const int kbeg = half * 384, kend = kbeg + 384;
        for (int k0 = kbeg; k0 < kend; k0 += 64) {
            #pragma unroll
            for (int it = 0; it < 16; it++) {
                int idx = it * 256 + tid;
                int bb = idx >> 6, k = idx & 63;
                int kg = k0 + k;
                Xs[k][bb] = (kg < DD) ? inputs[bb * DD + kg]
                                      : g_att[bb * HH + (kg - DD)];
            }
            #pragma unroll
            for (int it = 0; it < 4; it++) {
                int idx = it * 256 + tid;
                int jj = idx >> 6, k = idx & 63;
                Wsm[k][jj] = W_ih[(j0 + jj) * (DD + HH) + k0 + k];
            }
            __syncthreads();
            #pragma unroll
            for (int k = 0; k < 64; k++) {
                float w = Wsm[k][tx];
                #pragma unroll
                for (int i = 0; i < 4; i++)
                    acc[i] = fmaf(Xs[k][tb + 16 * i], w, acc[i]);
            }
            __syncthreads();
        }
        float* dst = half ? g_p1 : g_p0;
        #pragma unroll
        for (int i = 0; i < 4; i++)
            dst[(tb + 16 * i) * H3 + j] = acc[i];
    } else {
        const int kbeg = half * 256, kend = kbeg + 256;
        for (int k0 = kbeg; k0 < kend; k0 += 64) {
            #pragma unroll
            for (int it = 0; it < 16; it++) {
                int idx = it * 256 + tid;
                int bb = idx >> 6, k = idx & 63;
                Xs[k][bb] = states[bb * HH + k0 + k];
            }
            #pragma unroll
            for (int it = 0; it < 4; it++) {
                int idx = it * 256 + tid;
                int jj = idx >> 6, k = idx & 63;
                Wsm[k][jj] = W_hh[(j0 + jj) * HH + k0 + k];
            }
            __syncthreads();
            #pragma unroll
            for (int k = 0; k < 64; k++) {
                float w = Wsm[k][tx];
                #pragma unroll
                for (int i = 0; i < 4; i++)
                    acc[i] = fmaf(Xs[k][tb + 16 * i], w, acc[i]);
            }
            __syncthreads();
        }
        float* dst = half ? g_q1 : g_q0;
        #pragma unroll
        for (int i = 0; i < 4; i++)
            dst[(tb + 16 * i) * H3 + j] = acc[i];
    }
}

// ---------------- K5: GRU gates + output (sum partials + biases) --------------
__global__ void k5_gru(const float* __restrict__ states,
                       const float* __restrict__ b_ih,
                       const float* __restrict__ b_hh,
                       float* __restrict__ out) {
    const int b = blockIdx.x, h = threadIdx.x;
    const int o0 = b * H3 + h, o1 = o0 + HH, o2 = o1 + HH;
    const float ir = g_p0[o0] + g_p1[o0] + b_ih[h];
    const float iz = g_p0[o1] + g_p1[o1] + b_ih[HH + h];
    const float in_ = g_p0[o2] + g_p1[o2] + b_ih[2 * HH + h];
    const float hr = g_q0[o0] + g_q1[o0] + b_hh[h];
    const float hz = g_q0[o1] + g_q1[o1] + b_hh[HH + h];
    const float hn = g_q0[o2] + g_q1[o2] + b_hh[2 * HH + h];
    const float r = 1.f / (1.f + expf(-(ir + hr)));
    const float z = 1.f / (1.f + expf(-(iz + hz)));
    const float n = tanhf(in_ + r * hn);
    out[b * HH + h] = (1.f - z) * n + z * states[b * HH + h];
}

// ---------------- launch ------------------------------------------------------
extern "C" void kernel_launch(void* const* d_in, const int* in_sizes, int n_in,
                              void* d_out, int out_size) {
    const float* encoded = (const float*)d_in[0];
    const float* inputs  = (const float*)d_in[1];
    const float* states  = (const float*)d_in[2];
    const float* We      = (const float*)d_in[3];
    const float* be      = (const float*)d_in[4];
    const float* Wd      = (const float*)d_in[5];
    const float* bd      = (const float*)d_in[6];
    const float* Wv      = (const float*)d_in[7];
    const float* bv      = (const float*)d_in[8];
    const float* W_ih    = (const float*)d_in[9];
    const float* W_hh    = (const float*)d_in[10];
    const float* b_ih    = (const float*)d_in[11];
    const float* b_hh    = (const float*)d_in[12];
    float* out = (float*)d_out;

    cudaFuncSetAttribute(k2b_scores, cudaFuncAttributeMaxDynamicSharedMemorySize,
                         K2_SMEMB);

    k0_convW<<<32, 256>>>(We);
    k1_decproj<<<dim3(BB, 8), 128>>>(states, Wd, bd, be);
    k2b_scores<<<dim3(SS / 128, BB), 256, K2_SMEMB>>>(encoded, Wv, bv);
    k3a_softmax<<<BB, 1024>>>();
    k3b_att<<<dim3(HH / 128, SS / 256, BB), 256>>>(encoded);
    k4_gemm<<<dim3(H3 / 16, 4), 256>>>(inputs, states, W_ih, W_hh);
    k5_gru<<<BB, 512>>>(states, b_ih, b_hh, out);
}

// round 12
// speedup vs baseline: 1.0313x; 1.0313x over previous
#include <cuda_runtime.h>
#include <cuda_bf16.h>
#include <math.h>
#include <cstdint>

// Problem dims (fixed by the dataset)
#define BB 64
#define SS 1024
#define HH 512
#define AA 128
#define DD 256
#define H3 1536   // 3*HH

// ---------------- scratch (no allocations allowed -> device globals) ----------
__device__ float g_dec[BB * AA];
__device__ float g_scores[BB * SS];
__device__ float g_probs[BB * SS];
__device__ float g_att[BB * HH];
__device__ float g_p0[BB * H3];   // gi partial (K-half 0)
__device__ float g_p1[BB * H3];   // gi partial (K-half 1)
__device__ float g_q0[BB * H3];   // gh partial (K-half 0)
__device__ float g_q1[BB * H3];   // gh partial (K-half 1)
__device__ __align__(32) uint32_t g_We_bf[AA * HH / 2];   // We bf16 [a][k]

__device__ __forceinline__ float fast_tanh(float x) {
    float r;
    asm("tanh.approx.f32 %0, %1;" : "=f"(r) : "f"(x));
    return r;
}
__device__ __forceinline__ uint32_t smem_u32(const void* p) {
    uint32_t a;
    asm("{ .reg .u64 t; cvta.to.shared.u64 t, %1; cvt.u32.u64 %0, t; }"
        : "=r"(a) : "l"(p));
    return a;
}
__device__ __forceinline__ uint32_t pack_bf(float x, float y) {
    uint32_t r;
    asm("cvt.rn.bf16x2.f32 %0, %1, %2;" : "=r"(r) : "f"(y), "f"(x));
    return r;
}

// ---------------- K01: fused We->bf16 convert + dec_proj ----------------------
// grid (BB, 9), 128 threads. by==8: We conversion slice; by<8: dec_proj.
__global__ __launch_bounds__(128) void k01_prep(const float* __restrict__ states,
                                                const float* __restrict__ Wd,
                                                const float* __restrict__ bd,
                                                const float* __restrict__ be,
                                                const float* __restrict__ We) {
    if (blockIdx.y == 8) {
        // convert We rows [2b, 2b+2): 512 float2 per block, 4 per thread
        const int base = blockIdx.x * 512 + threadIdx.x * 4;
        const float2* W2 = (const float2*)We;
        #pragma unroll
        for (int i = 0; i < 4; i++) {
            float2 v = W2[base + i];
            g_We_bf[base + i] = pack_bf(v.x, v.y);
        }
        return;
    }
    const int b = blockIdx.x;
    const int a0 = blockIdx.y * 16 + (threadIdx.x >> 5) * 4;
    const int lane = threadIdx.x & 31;

    const float4* st4 = (const float4*)(states + b * HH);
    float4 st[4];
    #pragma unroll
    for (int j = 0; j < 4; j++) st[j] = st4[lane + 32 * j];

    #pragma unroll
    for (int i = 0; i < 4; i++) {
        const int a = a0 + i;
        const float4* w4 = (const float4*)(Wd + (size_t)a * HH);
        float s = 0.f;
        #pragma unroll
        for (int j = 0; j < 4; j++) {
            const float4 w = w4[lane + 32 * j];
            s += st[j].x * w.x + st[j].y * w.y + st[j].z * w.z + st[j].w * w.w;
        }
        #pragma unroll
        for (int o = 16; o; o >>= 1) s += __shfl_xor_sync(0xffffffffu, s, o);
        if (lane == 0) g_dec[b * AA + a] = s + bd[a] + be[a];
    }
}

// ======= K2b: fused fp32->bf16 mma.sync GEMM, double-buffered staging =========
// Block: 128 s x 128 a, K=512 in 8 chunks of 64.
// smem: fp32 staging 2x32KB (seg^(r&7) swizzle, conflict-free LDS.128),
//       bf16 E 1x16KB (SW128), W bf16 2x16KB. Total 114688 B -> 2 CTAs/SM.
// Pipeline: {E(c),W(c)} drained via wait_group 1 (E(c+1) stays in flight);
//           W(c+1), E(c+2) issued before MMA(c).
#define K2_F0    0
#define K2_F1    32768
#define K2_EB    65536
#define K2_WB    81920
#define K2_SMEMB 114688

__device__ __forceinline__ void cp16(uint32_t daddr, const void* src) {
    asm volatile("cp.async.cg.shared.global [%0], [%1], 16;" :: "r"(daddr), "l"(src));
}
__device__ __forceinline__ void cp_commit() {
    asm volatile("cp.async.commit_group;" ::: "memory");
}
__device__ __forceinline__ void ldsm4(uint32_t* r, uint32_t addr) {
    asm volatile("ldmatrix.sync.aligned.m8n8.x4.shared.b16 {%0,%1,%2,%3}, [%4];"
                 : "=r"(r[0]), "=r"(r[1]), "=r"(r[2]), "=r"(r[3]) : "r"(addr));
}
__device__ __forceinline__ void sts128(uint32_t addr, uint32_t a, uint32_t b,
                                       uint32_t c, uint32_t d) {
    asm volatile("st.shared.v4.b32 [%0], {%1,%2,%3,%4};"
                 :: "r"(addr), "r"(a), "r"(b), "r"(c), "r"(d));
}
__device__ __forceinline__ void lds128(float4& v, uint32_t addr) {
    asm volatile("ld.shared.v4.f32 {%0,%1,%2,%3}, [%4];"
                 : "=f"(v.x), "=f"(v.y), "=f"(v.z), "=f"(v.w) : "r"(addr));
}
__device__ __forceinline__ void mma_bf16(float* d, const uint32_t* a,
                                         uint32_t b0, uint32_t b1) {
    asm volatile(
        "mma.sync.aligned.m16n8k16.row.col.f32.bf16.bf16.f32 "
        "{%0,%1,%2,%3}, {%4,%5,%6,%7}, {%8,%9}, {%0,%1,%2,%3};"
        : "+f"(d[0]), "+f"(d[1]), "+f"(d[2]), "+f"(d[3])
        : "r"(a[0]), "r"(a[1]), "r"(a[2]), "r"(a[3]), "r"(b0), "r"(b1));
}

__global__ __launch_bounds__(256, 2) void k2b_scores(const float* __restrict__ enc,
                                                     const float* __restrict__ Wv,
                                                     const float* __restrict__ bv) {
    extern __shared__ float sm[];
    const uint32_t smem_base = smem_u32(sm);
    float* sp = sm;   // reused staging area post-mainloop (2*128 floats)

    const int b  = blockIdx.y;
    const int s0 = blockIdx.x * 128;
    const int tid = threadIdx.x;
    const int lane = tid & 31;
    const int wid = tid >> 5;
    const int warp_s = wid & 3;
    const int warp_a = wid >> 2;
    const int ms = warp_s * 32;
    const int na = warp_a * 64;

    const char* encb = (const char*)(enc + ((size_t)b * SS + s0) * HH);
    const char* web  = (const char*)g_We_bf;
    const int r_st  = tid >> 3;   // 0..31 (+32i)
    const int sg_st = tid & 7;    // 16B segment 0..7

    float acc[2][8][4];
    #pragma unroll
    for (int f = 0; f < 2; f++)
        #pragma unroll
        for (int g = 0; g < 8; g++)
            #pragma unroll
            for (int q = 0; q < 4; q++) acc[f][g][q] = 0.f;

    // fp32 E chunk load: 128 rows x 256B = 16 segs, swizzled seg^(r&7)
    auto issueE = [&](int c) {
        const uint32_t fb = smem_base + ((c & 1) ? K2_F1 : K2_F0);
        #pragma unroll
        for (int i = 0; i < 8; i++) {
            const int g2 = i * 256 + tid;
            const int r = g2 >> 4;
            const int s = g2 & 15;
            cp16(fb + r * 256 + ((s ^ (r & 7)) << 4),
                 encb + (size_t)r * 2048 + c * 256 + s * 16);
        }
    };
    // W bf16 chunk load (SW128)
    auto issueW = [&](int c) {
        const uint32_t wb = smem_base + K2_WB + (c & 1) * 16384;
        #pragma unroll
        for (int i = 0; i < 4; i++) {
            const int r = r_st + i * 32;
            cp16(wb + r * 128 + ((sg_st ^ (r & 7)) << 4),
                 web + (size_t)r * 1024 + c * 128 + sg_st * 16);
        }
    };

    const int rr   = tid & 127;
    const int half = tid >> 7;

    // prologue: P0 = {E0, W0}; P1 = {E1}
    issueE(0); issueW(0); cp_commit();
    issueE(1); cp_commit();

    #pragma unroll
    for (int c = 0; c < 8; c++) {
        if (c < 7) asm volatile("cp.async.wait_group 1;" ::: "memory");
        else       asm volatile("cp.async.wait_group 0;" ::: "memory");
        __syncthreads();

        // convert fbuf[c&1] (fp32) -> Eb (bf16, SW128); transient regs only
        {
            const uint32_t fsrc = smem_base + ((c & 1) ? K2_F1 : K2_F0) + rr * 256;
            float4 f[8];
            #pragma unroll
            for (int j = 0; j < 8; j++)
                lds128(f[j], fsrc + (((half * 8 + j) ^ (rr & 7)) << 4));
            uint32_t u[16];
            #pragma unroll
            for (int j = 0; j < 8; j++) {
                u[2 * j]     = pack_bf(f[j].x, f[j].y);
                u[2 * j + 1] = pack_bf(f[j].z, f[j].w);
            }
            const uint32_t ebase = smem_base + K2_EB + rr * 128;
            #pragma unroll
            for (int j2 = 0; j2 < 4; j2++) {
                const int seg = half * 4 + j2;
                sts128(ebase + ((seg ^ (rr & 7)) << 4),
                       u[4 * j2], u[4 * j2 + 1], u[4 * j2 + 2], u[4 * j2 + 3]);
            }
        }
        __syncthreads();

        if (c < 7) { issueW(c + 1); cp_commit(); }
        if (c < 6) { issueE(c + 2); cp_commit(); }

        const uint32_t Eb = smem_base + K2_EB;
        const uint32_t Wb = smem_base + K2_WB + (c & 1) * 16384;
        #pragma unroll
        for (int ks = 0; ks < 4; ks++) {
            uint32_t afr[2][4];
            #pragma unroll
            for (int f = 0; f < 2; f++) {
                const int row = ms + f * 16 + (lane & 15);
                const int seg = ks * 2 + (lane >> 4);
                ldsm4(afr[f], Eb + row * 128 + ((seg ^ (row & 7)) << 4));
            }
            #pragma unroll
            for (int g2 = 0; g2 < 4; g2++) {
                const int row = na + g2 * 16 + ((lane >> 4) << 3) + (lane & 7);
                const int seg = ks * 2 + ((lane >> 3) & 1);
                uint32_t bfr[4];
                ldsm4(bfr, Wb + row * 128 + ((seg ^ (row & 7)) << 4));
                mma_bf16(acc[0][2 * g2],     afr[0], bfr[0], bfr[1]);
                mma_bf16(acc[0][2 * g2 + 1], afr[0], bfr[2], bfr[3]);
                mma_bf16(acc[1][2 * g2],     afr[1], bfr[0], bfr[1]);
                mma_bf16(acc[1][2 * g2 + 1], afr[1], bfr[2], bfr[3]);
            }
        }
    }
    __syncthreads();   // all MMA done; staging area reusable as sp

    // epilogue: tanh(acc + dec) * wv, reduce over a (dec/wv from L2-hot global)
    #pragma unroll
    for (int f = 0; f < 2; f++) {
        float pl = 0.f, ph = 0.f;
        #pragma unroll
        for (int g = 0; g < 8; g++) {
            const int a0 = warp_a * 64 + g * 8 + (lane & 3) * 2;
            const float d0 = __ldg(g_dec + b * AA + a0);
            const float d1 = __ldg(g_dec + b * AA + a0 + 1);
            const float w0 = __ldg(Wv + a0);
            const float w1 = __ldg(Wv + a0 + 1);
            pl += fast_tanh(acc[f][g][0] + d0) * w0 + fast_tanh(acc[f][g][1] + d1) * w1;
            ph += fast_tanh(acc[f][g][2] + d0) * w0 + fast_tanh(acc[f][g][3] + d1) * w1;
        }
        pl += __shfl_xor_sync(0xffffffffu, pl, 1);
        pl += __shfl_xor_sync(0xffffffffu, pl, 2);
        ph += __shfl_xor_sync(0xffffffffu, ph, 1);
        ph += __shfl_xor_sync(0xffffffffu, ph, 2);
        if ((lane & 3) == 0) {
            const int sl = ms + f * 16 + (lane >> 2);
            sp[warp_a * 128 + sl]     = pl;
            sp[warp_a * 128 + sl + 8] = ph;
        }
    }
    __syncthreads();
    if (tid < 128)
        g_scores[b * SS + s0 + tid] = sp[tid] + sp[128 + tid] + bv[0];
}

// ---------------- K3a: softmax over seq per batch (+ zero g_att) --------------
__global__ __launch_bounds__(1024) void k3a_softmax() {
    const int b = blockIdx.x, tid = threadIdx.x;
    const int lane = tid & 31, warp = tid >> 5;
    __shared__ float red[32];
    __shared__ float bcast;

    if (tid < HH) g_att[b * HH + tid] = 0.f;

    float v = g_scores[b * SS + tid];

    float m = v;
    #pragma unroll
    for (int o = 16; o; o >>= 1) m = fmaxf(m, __shfl_xor_sync(0xffffffffu, m, o));
    if (lane == 0) red[warp] = m;
    __syncthreads();
    if (warp == 0) {
        float t = red[lane];
        #pragma unroll
        for (int o = 16; o; o >>= 1) t = fmaxf(t, __shfl_xor_sync(0xffffffffu, t, o));
        if (lane == 0) bcast = t;
    }
    __syncthreads();
    const float mx = bcast;

    const float e = expf(v - mx);
    float s = e;
    #pragma unroll
    for (int o = 16; o; o >>= 1) s += __shfl_xor_sync(0xffffffffu, s, o);
    __syncthreads();
    if (lane == 0) red[warp] = s;
    __syncthreads();
    if (warp == 0) {
        float t = red[lane];
        #pragma unroll
        for (int o = 16; o; o >>= 1) t += __shfl_xor_sync(0xffffffffu, t, o);
        if (lane == 0) bcast = 1.f / t;
    }
    __syncthreads();
    g_probs[b * SS + tid] = e * bcast;
}

// ---------------- K3b: attention from fp32 enc --------------------------------
__global__ __launch_bounds__(256) void k3b_att(const float* __restrict__ enc) {
    const int b  = blockIdx.z;
    const int sb = blockIdx.y;
    const int hb = blockIdx.x;
    const int lane = threadIdx.x & 31;
    const int srow = threadIdx.x >> 5;
    const float* e = enc + ((size_t)b * SS + sb * 256 + srow) * HH + hb * 128 + lane * 4;
    const float* pr = g_probs + b * SS + sb * 256 + srow;

    float4 a0 = {0.f, 0.f, 0.f, 0.f}, a1 = {0.f, 0.f, 0.f, 0.f};
    #pragma unroll 4
    for (int i = 0; i < 32; i += 2) {
        const float p0 = pr[i * 8];
        const float p1 = pr[(i + 1) * 8];
        const float4 v0 = *(const float4*)(e + (size_t)i * 8 * HH);
        const float4 v1 = *(const float4*)(e + (size_t)(i + 1) * 8 * HH);
        a0.x = fmaf(p0, v0.x, a0.x); a0.y = fmaf(p0, v0.y, a0.y);
        a0.z = fmaf(p0, v0.z, a0.z); a0.w = fmaf(p0, v0.w, a0.w);
        a1.x = fmaf(p1, v1.x, a1.x); a1.y = fmaf(p1, v1.y, a1.y);
        a1.z = fmaf(p1, v1.z, a1.z); a1.w = fmaf(p1, v1.w, a1.w);
    }
    a0.x += a1.x; a0.y += a1.y; a0.z += a1.z; a0.w += a1.w;

    __shared__ float red[8][32][4];
    red[srow][lane][0] = a0.x;
    red[srow][lane][1] = a0.y;
    red[srow][lane][2] = a0.z;
    red[srow][lane][3] = a0.w;
    __syncthreads();
    if (threadIdx.x < 128) {
        const int l = threadIdx.x & 31;
        const int comp = threadIdx.x >> 5;
        float s = 0.f;
        #pragma unroll
        for (int r = 0; r < 8; r++) s += red[r][l][comp];
        atomicAdd(&g_att[b * HH + hb * 128 + l * 4 + comp], s);
    }
}

// ---------------- K4: gate GEMMs, phase x K-half split, partial buffers -------
__global__ __launch_bounds__(256) void k4_gemm(const float* __restrict__ inputs,
                                               const float* __restrict__ states,
                                               const float* __restrict__ W_ih,
                                               const float* __restrict__ W_hh) {
    const int j0 = blockIdx.x * 16;
    const int phase = blockIdx.y >> 1;
    const int half  = blockIdx.y & 1;
    const int tid = threadIdx.x;
    const int tx = tid & 15;
    const int tb = tid >> 4;
    const int j = j0 + tx;
    __shared__ float Xs[64][65];
    __shared__ float Wsm[64][17];

    float acc[4] = {0.f, 0.f, 0.f, 0.f};
    if (phase == 0) {
        const int kbeg = half * 384, kend = kbeg + 384;
        for (int k0 = kbeg; k0 < kend; k0 += 64) {
            #pragma unroll
            for (int it = 0; it < 16; it++) {
                int idx = it * 256 + tid;
                int bb = idx >> 6, k = idx & 63;
                int kg = k0 + k;
                Xs[k][bb] = (kg < DD) ? inputs[bb * DD + kg]
                                      : g_att[bb * HH + (kg - DD)];
            }
            #pragma unroll
            for (int it = 0; it < 4; it++) {
                int idx = it * 256 + tid;
                int jj = idx >> 6, k = idx & 63;
                Wsm[k][jj] = W_ih[(j0 + jj) * (DD + HH) + k0 + k];
            }
            __syncthreads();
            #pragma unroll
            for (int k = 0; k < 64; k++) {
                float w = Wsm[k][tx];
                #pragma unroll
                for (int i = 0; i < 4; i++)
                    acc[i] = fmaf(Xs[k][tb + 16 * i], w, acc[i]);
            }
            __syncthreads();
        }
        float* dst = half ? g_p1 : g_p0;
        #pragma unroll
        for (int i = 0; i < 4; i++)
            dst[(tb + 16 * i) * H3 + j] = acc[i];
    } else {
        const int kbeg = half * 256, kend = kbeg + 256;
        for (int k0 = kbeg; k0 < kend; k0 += 64) {
            #pragma unroll
            for (int it = 0; it < 16; it++) {
                int idx = it * 256 + tid;
                int bb = idx >> 6, k = idx & 63;
                Xs[k][bb] = states[bb * HH + k0 + k];
            }
            #pragma unroll
            for (int it = 0; it < 4; it++) {
                int idx = it * 256 + tid;
                int jj = idx >> 6, k = idx & 63;
                Wsm[k][jj] = W_hh[(j0 + jj) * HH + k0 + k];
            }
            __syncthreads();
            #pragma unroll
            for (int k = 0; k < 64; k++) {
                float w = Wsm[k][tx];
                #pragma unroll
                for (int i = 0; i < 4; i++)
                    acc[i] = fmaf(Xs[k][tb + 16 * i], w, acc[i]);
            }
            __syncthreads();
        }
        float* dst = half ? g_q1 : g_q0;
        #pragma unroll
        for (int i = 0; i < 4; i++)
            dst[(tb + 16 * i) * H3 + j] = acc[i];
    }
}

// ---------------- K5: GRU gates + output (sum partials + biases) --------------
__global__ void k5_gru(const float* __restrict__ states,
                       const float* __restrict__ b_ih,
                       const float* __restrict__ b_hh,
                       float* __restrict__ out) {
    const int b = blockIdx.x, h = threadIdx.x;
    const int o0 = b * H3 + h, o1 = o0 + HH, o2 = o1 + HH;
    const float ir = g_p0[o0] + g_p1[o0] + b_ih[h];
    const float iz = g_p0[o1] + g_p1[o1] + b_ih[HH + h];
    const float in_ = g_p0[o2] + g_p1[o2] + b_ih[2 * HH + h];
    const float hr = g_q0[o0] + g_q1[o0] + b_hh[h];
    const float hz = g_q0[o1] + g_q1[o1] + b_hh[HH + h];
    const float hn = g_q0[o2] + g_q1[o2] + b_hh[2 * HH + h];
    const float r = 1.f / (1.f + expf(-(ir + hr)));
    const float z = 1.f / (1.f + expf(-(iz + hz)));
    const float n = tanhf(in_ + r * hn);
    out[b * HH + h] = (1.f - z) * n + z * states[b * HH + h];
}

// ---------------- launch ------------------------------------------------------
extern "C" void kernel_launch(void* const* d_in, const int* in_sizes, int n_in,
                              void* d_out, int out_size) {
    const float* encoded = (const float*)d_in[0];
    const float* inputs  = (const float*)d_in[1];
    const float* states  = (const float*)d_in[2];
    const float* We      = (const float*)d_in[3];
    const float* be      = (const float*)d_in[4];
    const float* Wd      = (const float*)d_in[5];
    const float* bd      = (const float*)d_in[6];
    const float* Wv      = (const float*)d_in[7];
    const float* bv      = (const float*)d_in[8];
    const float* W_ih    = (const float*)d_in[9];
    const float* W_hh    = (const float*)d_in[10];
    const float* b_ih    = (const float*)d_in[11];
    const float* b_hh    = (const float*)d_in[12];
    float* out = (float*)d_out;

    cudaFuncSetAttribute(k2b_scores, cudaFuncAttributeMaxDynamicSharedMemorySize,
                         K2_SMEMB);

    k01_prep<<<dim3(BB, 9), 128>>>(states, Wd, bd, be, We);
    k2b_scores<<<dim3(SS / 128, BB), 256, K2_SMEMB>>>(encoded, Wv, bv);
    k3a_softmax<<<BB, 1024>>>();
    k3b_att<<<dim3(HH / 128, SS / 256, BB), 256>>>(encoded);
    k4_gemm<<<dim3(H3 / 16, 4), 256>>>(inputs, states, W_ih, W_hh);
    k5_gru<<<BB, 512>>>(states, b_ih, b_hh, out);
}